// round 2
// baseline (speedup 1.0000x reference)
#include <cuda_runtime.h>
#include <cuda_bf16.h>

#define BB    4096   // batch
#define TT    80     // seq len
#define HH    256    // hidden
#define DIN   8      // embed dim
#define VV    80     // vocab
#define G4H   1024   // 4*H

#define BH    (BB*HH)
#define OFF_H (BB*VV)                 // 327680
#define OFF_C (OFF_H + 2*BH)          // 327680 + 2097152

// ---------------- device scratch (no allocation allowed) ----------------
__device__ float g_Wp1[G4H * 264];    // layer1 packed [n=4j+g][k: 0..7 emb, 8..263 hh]
__device__ float g_Wp2[G4H * 512];    // layer2 packed [n][k: 0..255 ih(h1), 256..511 hh(h2)]
__device__ float g_h1[2][BH];
__device__ float g_h2[2][BH];
__device__ float g_c1[BH];
__device__ float g_c2[BH];

// ---------------- f32x2 helpers (Blackwell packed FMA) ----------------
__device__ __forceinline__ unsigned long long pk2(float lo, float hi) {
    unsigned long long r;
    asm("mov.b64 %0, {%1, %2};" : "=l"(r) : "f"(lo), "f"(hi));
    return r;
}
__device__ __forceinline__ void unpk2(unsigned long long v, float& lo, float& hi) {
    asm("mov.b64 {%0, %1}, %2;" : "=f"(lo), "=f"(hi) : "l"(v));
}
__device__ __forceinline__ void ffma2(unsigned long long& d, unsigned long long a, unsigned long long b) {
    asm("fma.rn.f32x2 %0, %1, %2, %0;" : "+l"(d) : "l"(a), "l"(b));
}

__device__ __forceinline__ float sigf(float x) {
    return 1.0f / (1.0f + __expf(-x));
}
__device__ __forceinline__ float tanhp(float x) {
    // tanh(x) = 2*sigmoid(2x) - 1 ; abs err ~2e-7, fine for 1e-3 tolerance
    return 2.0f * sigf(2.0f * x) - 1.0f;
}

// ---------------- weight packing ----------------
__global__ void pack_w1(const float* __restrict__ Wih0, const float* __restrict__ Whh0) {
    int idx = blockIdx.x * 256 + threadIdx.x;
    if (idx < G4H * 264) {
        int n = idx / 264, k = idx % 264;
        int row = (n & 3) * HH + (n >> 2);    // original row = g*H + j
        g_Wp1[idx] = (k < DIN) ? Wih0[row * DIN + k] : Whh0[row * HH + (k - DIN)];
    }
}
__global__ void pack_w2(const float* __restrict__ Wih1, const float* __restrict__ Whh1) {
    int idx = blockIdx.x * 256 + threadIdx.x;
    if (idx < G4H * 512) {
        int n = idx / 512, k = idx % 512;
        int row = (n & 3) * HH + (n >> 2);
        g_Wp2[idx] = (k < HH) ? Wih1[row * HH + k] : Whh1[row * HH + (k - HH)];
    }
}

__global__ void init_state(const float* __restrict__ h0, const float* __restrict__ c0) {
    int i = blockIdx.x * 256 + threadIdx.x;
    if (i < BH) {
        g_h1[0][i] = h0[i];
        g_h2[0][i] = h0[BH + i];
        g_c1[i]    = c0[i];
        g_c2[i]    = c0[BH + i];
    }
}

// ---------------- fused LSTM step: GEMM(128x128x8 tiles, f32x2) + gate epilogue ----
// C[b][n] = sum_k A[b][k] * Wp[n][k], n = 4j+g, then per (b,j) LSTM update.
// LAYER==0: A = [emb(x[b,t]) | h1_prev], K=264, SPLIT=8
// LAYER==1: A = [h1_cur | h2_prev],      K=512, SPLIT=256
template<int KTOT, int SPLIT, int LAYER>
__global__ void __launch_bounds__(256, 2) lstm_step(
    const float* __restrict__ emb, const int* __restrict__ x, int t, int p)
{
    __shared__ float As[8][132];
    __shared__ float Bs[8][132];

    const float* __restrict__ W     = (LAYER == 0) ? g_Wp1      : g_Wp2;
    const float* __restrict__ hprev = (LAYER == 0) ? g_h1[p]    : g_h2[p];
    float*       __restrict__ hout  = (LAYER == 0) ? g_h1[p^1]  : g_h2[p^1];
    float*       __restrict__ cst   = (LAYER == 0) ? g_c1       : g_c2;

    const int tid = threadIdx.x;
    const int ra  = tid >> 1;            // 0..127 : row loaded by this thread
    const int ka  = (tid & 1) * 4;       // 0 or 4 : k offset within 8-tile
    const int arow = blockIdx.y * 128 + ra;
    const int wrow = blockIdx.x * 128 + ra;

    const float* base0;
    if (LAYER == 0) base0 = emb + x[arow * TT + t] * DIN;
    else            base0 = g_h1[p ^ 1] + arow * HH;     // h1 at current t
    const float* base1 = hprev + arow * HH - SPLIT;
    const float* wbase = W + wrow * KTOT;

    unsigned long long acc[8][4];
    #pragma unroll
    for (int i = 0; i < 8; i++)
        #pragma unroll
        for (int j = 0; j < 4; j++) acc[i][j] = 0ULL;   // two packed 0.0f

    const int tx = tid & 15, ty = tid >> 4;

    for (int kt = 0; kt < KTOT; kt += 8) {
        const float* ab = (kt < SPLIT) ? base0 : base1;
        float4 av = *(const float4*)(ab + kt + ka);
        float4 bv = *(const float4*)(wbase + kt + ka);
        __syncthreads();
        As[ka+0][ra] = av.x; As[ka+1][ra] = av.y; As[ka+2][ra] = av.z; As[ka+3][ra] = av.w;
        Bs[ka+0][ra] = bv.x; Bs[ka+1][ra] = bv.y; Bs[ka+2][ra] = bv.z; Bs[ka+3][ra] = bv.w;
        __syncthreads();

        #pragma unroll
        for (int kk = 0; kk < 8; kk++) {
            float4 a0 = *(const float4*)&As[kk][ty * 8];
            float4 a1 = *(const float4*)&As[kk][ty * 8 + 4];
            ulonglong2 b0 = *(const ulonglong2*)&Bs[kk][tx * 8];
            ulonglong2 b1 = *(const ulonglong2*)&Bs[kk][tx * 8 + 4];
            unsigned long long bb[4] = { b0.x, b0.y, b1.x, b1.y };
            float aa[8] = { a0.x, a0.y, a0.z, a0.w, a1.x, a1.y, a1.z, a1.w };
            #pragma unroll
            for (int i = 0; i < 8; i++) {
                unsigned long long ad = pk2(aa[i], aa[i]);
                #pragma unroll
                for (int j = 0; j < 4; j++) ffma2(acc[i][j], ad, bb[j]);
            }
        }
    }

    // Epilogue: each thread owns 8 b-rows x 2 j-columns, with all 4 gates local.
    const int bbase = blockIdx.y * 128 + ty * 8;
    const int jb    = blockIdx.x * 32 + tx * 2;
    #pragma unroll
    for (int i = 0; i < 8; i++) {
        const int b = bbase + i;
        #pragma unroll
        for (int jj = 0; jj < 2; jj++) {
            float gi, gf, gg, go;
            unpk2(acc[i][2*jj + 0], gi, gf);
            unpk2(acc[i][2*jj + 1], gg, go);
            const int j = jb + jj;
            const int idx = b * HH + j;
            float co = cst[idx];
            float cn = sigf(gf) * co + sigf(gi) * tanhp(gg);
            cst[idx]  = cn;
            hout[idx] = sigf(go) * tanhp(cn);
        }
    }
}

// ---------------- final FC: logits[b][v] = h2_T[b] . fc_W[v] + fc_b[v] ----------------
__global__ void fc_kernel(const float* __restrict__ Wf, const float* __restrict__ bf,
                          float* __restrict__ out)
{
    __shared__ float hs[8][HH];
    const int b0 = blockIdx.x * 8;
    const float* __restrict__ h2 = g_h2[0];  // final h2 lives in buffer 0 (T even)
    for (int i = threadIdx.x; i < 8 * HH; i += 256)
        hs[i / HH][i % HH] = h2[(b0 + i / HH) * HH + (i % HH)];
    __syncthreads();
    for (int idx = threadIdx.x; idx < 8 * VV; idx += 256) {
        const int bl = idx / VV, v = idx % VV;
        const float* __restrict__ wr = Wf + v * HH;
        const float* __restrict__ hp = hs[bl];
        float s = bf[v];
        #pragma unroll 8
        for (int k = 0; k < HH; k++) s += hp[k] * wr[k];
        out[(b0 + bl) * VV + v] = s;
    }
}

__global__ void finalize(float* __restrict__ out) {
    int i = blockIdx.x * 256 + threadIdx.x;
    if (i < BH) {
        out[OFF_H + i]      = g_h1[0][i];
        out[OFF_H + BH + i] = g_h2[0][i];
        out[OFF_C + i]      = g_c1[i];
        out[OFF_C + BH + i] = g_c2[i];
    }
}

// ---------------- launch ----------------
extern "C" void kernel_launch(void* const* d_in, const int* in_sizes, int n_in,
                              void* d_out, int out_size)
{
    const int*   x    = (const int*)  d_in[0];
    const float* h0   = (const float*)d_in[1];
    const float* c0   = (const float*)d_in[2];
    const float* emb  = (const float*)d_in[3];
    const float* Wih0 = (const float*)d_in[4];
    const float* Whh0 = (const float*)d_in[5];
    const float* Wih1 = (const float*)d_in[6];
    const float* Whh1 = (const float*)d_in[7];
    const float* fcW  = (const float*)d_in[8];
    const float* fcb  = (const float*)d_in[9];
    float* out = (float*)d_out;

    pack_w1<<<(G4H * 264 + 255) / 256, 256>>>(Wih0, Whh0);
    pack_w2<<<(G4H * 512 + 255) / 256, 256>>>(Wih1, Whh1);
    init_state<<<(BH + 255) / 256, 256>>>(h0, c0);

    dim3 grid(8, 32);   // 8 n-tiles (1024/128) x 32 m-tiles (4096/128)
    for (int t = 0; t < TT; t++) {
        const int p = t & 1;
        lstm_step<264, 8,   0><<<grid, 256>>>(emb, x, t, p);
        lstm_step<512, 256, 1><<<grid, 256>>>(emb, x, t, p);
    }

    fc_kernel<<<BB / 8, 256>>>(fcW, fcb, out);
    finalize<<<(BH + 255) / 256, 256>>>(out);
}

// round 4
// speedup vs baseline: 2.5301x; 2.5301x over previous
#include <cuda_runtime.h>
#include <cuda_bf16.h>
#include <cstdint>

#define BB    4096
#define TT    80
#define HH    256
#define DIN   8
#define VV    80
#define G4H   1024
#define BH    (BB*HH)
#define OFF_H (BB*VV)
#define OFF_C (OFF_H + 2*BH)

// ---------------- device scratch (no allocation allowed) ----------------
__device__ __nv_bfloat16 g_W1hi[G4H*256], g_W1lo[G4H*256];   // layer1 hh, packed cols, K contig
__device__ __nv_bfloat16 g_W2hi[G4H*512], g_W2lo[G4H*512];   // layer2 [ih | hh]
__device__ float         g_bias1[VV*G4H];                     // (W_ih0 @ emb[v]) in packed col order
__device__ __nv_bfloat16 g_h1hi[2][BH], g_h1lo[2][BH];
__device__ __nv_bfloat16 g_h2hi[2][BH], g_h2lo[2][BH];
__device__ float         g_c1[BH], g_c2[BH];

// packed column m -> original gate row (g*H + j)
// chosen so one thread's HMMA accum cols over a tile-pair = gates i,f,g,o of one j
__host__ __device__ __forceinline__ int orig_row(int m) {
    int j = 4 * (m >> 4) + ((m >> 1) & 3);
    int g = (m & 1) | (((m >> 3) & 1) << 1);
    return g * HH + j;
}

// ---------------- PTX helpers (sm_80-era features only: safe on sm_103) ----------------
__device__ __forceinline__ uint32_t smem_u32(const void* p) {
    uint32_t a;
    asm("{ .reg .u64 t; cvta.to.shared.u64 t, %1; cvt.u32.u64 %0, t; }" : "=r"(a) : "l"(p));
    return a;
}
__device__ __forceinline__ void cpa16(uint32_t s, const void* g) {
    asm volatile("cp.async.cg.shared.global [%0], [%1], 16;" :: "r"(s), "l"(g));
}
__device__ __forceinline__ void cpa_commit() {
    asm volatile("cp.async.commit_group;" ::: "memory");
}
template<int N>
__device__ __forceinline__ void cpa_wait() {
    asm volatile("cp.async.wait_group %0;" :: "n"(N) : "memory");
}
__device__ __forceinline__ void ldsm4(uint32_t* r, uint32_t addr) {
    asm volatile("ldmatrix.sync.aligned.m8n8.x4.shared.b16 {%0,%1,%2,%3}, [%4];"
                 : "=r"(r[0]), "=r"(r[1]), "=r"(r[2]), "=r"(r[3]) : "r"(addr));
}
__device__ __forceinline__ void mma16816(float* c, const uint32_t* a, uint32_t b0, uint32_t b1) {
    asm volatile(
        "mma.sync.aligned.m16n8k16.row.col.f32.bf16.bf16.f32 "
        "{%0,%1,%2,%3}, {%4,%5,%6,%7}, {%8,%9}, {%0,%1,%2,%3};"
        : "+f"(c[0]), "+f"(c[1]), "+f"(c[2]), "+f"(c[3])
        : "r"(a[0]), "r"(a[1]), "r"(a[2]), "r"(a[3]), "r"(b0), "r"(b1));
}

__device__ __forceinline__ float sigf(float x)  { return 1.0f / (1.0f + __expf(-x)); }
__device__ __forceinline__ float tanhp(float x) { return 2.0f * sigf(2.0f * x) - 1.0f; }

// SMEM buffer layout (per stage, stride 49152):
//   Ahi 16K | Alo 16K | Bhi 8K | Blo 8K   (128B rows, SW128 swizzle)
#define STG 49152
#define SMEM_TOTAL (2*STG)

// =========================================================================
// Fused HMMA LSTM step.
//   LAYER 0: K=256 (NC=4), A = h1[p],    bias table per token
//   LAYER 1: K=512 (NC=8), A = [h1_cur | h2_prev]
// CTA tile: M=128 x N=64 packed cols. 8 warps (4 M x 2 N) of 32x32.
// =========================================================================
template<int NC, int LAYER>
__global__ void __launch_bounds__(256, 2) lstm_mma(const int* __restrict__ x, int t, int p)
{
    extern __shared__ char sm[];
    const uint32_t smb = smem_u32(sm);
    const int tid  = threadIdx.x;
    const int lane = tid & 31, wid = tid >> 5;
    const int wm = wid & 3, wn = wid >> 2;
    const int bx = blockIdx.x;             // 0..15 n-tiles
    const int by = blockIdx.y;             // 0..31 m-tiles
    const int mbase = by * 128, nb = bx * 64;
    constexpr int KW = NC * 64;

    const __nv_bfloat16 *A0hi, *A0lo, *A1hi, *A1lo, *Whi, *Wlo;
    __nv_bfloat16 *Ohi, *Olo;
    float* cst;
    if (LAYER == 0) {
        A0hi = g_h1hi[p];   A0lo = g_h1lo[p];   A1hi = A0hi;       A1lo = A0lo;
        Whi = g_W1hi; Wlo = g_W1lo; cst = g_c1;
        Ohi = g_h1hi[p^1];  Olo = g_h1lo[p^1];
    } else {
        A0hi = g_h1hi[p^1]; A0lo = g_h1lo[p^1];   // h1 at current t
        A1hi = g_h2hi[p];   A1lo = g_h2lo[p];     // h2 at t-1
        Whi = g_W2hi; Wlo = g_W2lo; cst = g_c2;
        Ohi = g_h2hi[p^1];  Olo = g_h2lo[p^1];
    }

    float acc[2][4][4];
    #pragma unroll
    for (int i = 0; i < 2; i++)
        #pragma unroll
        for (int j = 0; j < 4; j++)
            #pragma unroll
            for (int k = 0; k < 4; k++) acc[i][j][k] = 0.f;

    // ---- async chunk loader ----
    auto load_chunk = [&](int c) {
        const int s = c & 1;
        const uint32_t sb = smb + s * STG;
        const __nv_bfloat16* ahi = (LAYER == 0 || c < 4) ? A0hi : A1hi;
        const __nv_bfloat16* alo = (LAYER == 0 || c < 4) ? A0lo : A1lo;
        const int ko = (c & 3) * 64;
        #pragma unroll
        for (int it = 0; it < 4; ++it) {                 // A: 128 rows x 8 chunks
            const int idx = tid + it * 256;
            const int row = idx >> 3, ch = idx & 7;
            const uint32_t so = (uint32_t)((row * 128 + ch * 16) ^ ((row & 7) << 4));
            const int go = (mbase + row) * HH + ko + ch * 8;
            cpa16(sb + so,         ahi + go);
            cpa16(sb + 16384 + so, alo + go);
        }
        #pragma unroll
        for (int it = 0; it < 2; ++it) {                 // B: 64 rows x 8 chunks
            const int idx = tid + it * 256;
            const int row = idx >> 3, ch = idx & 7;
            const uint32_t so = (uint32_t)((row * 128 + ch * 16) ^ ((row & 7) << 4));
            const int gw = (nb + row) * KW + c * 64 + ch * 8;
            cpa16(sb + 32768 + so, Whi + gw);
            cpa16(sb + 40960 + so, Wlo + gw);
        }
        cpa_commit();
    };

    load_chunk(0);
    for (int c = 0; c < NC; ++c) {
        if (c + 1 < NC) { load_chunk(c + 1); cpa_wait<1>(); }
        else            { cpa_wait<0>(); }
        __syncthreads();

        const uint32_t sb = smb + (c & 1) * STG;
        #pragma unroll
        for (int ks = 0; ks < 4; ++ks) {
            uint32_t ahf[2][4], alf[2][4];
            #pragma unroll
            for (int mt = 0; mt < 2; ++mt) {
                const int row  = wm * 32 + mt * 16 + (lane & 15);
                const int koff = ks * 32 + ((lane >> 4) & 1) * 16;
                const uint32_t so = (uint32_t)((row * 128 + koff) ^ ((row & 7) << 4));
                ldsm4(ahf[mt], sb + so);
                ldsm4(alf[mt], sb + 16384 + so);
            }
            uint32_t bhf[2][4], blf[2][4];
            #pragma unroll
            for (int np = 0; np < 2; ++np) {
                const int row  = wn * 32 + np * 16 + (lane & 7) + ((lane >> 4) & 1) * 8;
                const int koff = ks * 32 + ((lane >> 3) & 1) * 16;
                const uint32_t so = (uint32_t)((row * 128 + koff) ^ ((row & 7) << 4));
                ldsm4(bhf[np], sb + 32768 + so);
                ldsm4(blf[np], sb + 40960 + so);
            }
            #pragma unroll
            for (int mt = 0; mt < 2; ++mt)
                #pragma unroll
                for (int nt = 0; nt < 4; ++nt) {
                    const int np = nt >> 1, hf = (nt & 1) * 2;
                    mma16816(acc[mt][nt], ahf[mt], bhf[np][hf], bhf[np][hf + 1]);
                    mma16816(acc[mt][nt], ahf[mt], blf[np][hf], blf[np][hf + 1]);
                    mma16816(acc[mt][nt], alf[mt], bhf[np][hf], bhf[np][hf + 1]);
                }
        }
        __syncthreads();
    }

    // ---- fused LSTM epilogue: all 4 gates of (b, j) live in this thread ----
    const int r = lane >> 2, q = lane & 3;
    #pragma unroll
    for (int mt = 0; mt < 2; ++mt) {
        const int b0 = mbase + wm * 32 + mt * 16 + r;
        int v0 = 0, v1 = 0;
        if (LAYER == 0) { v0 = x[b0 * TT + t]; v1 = x[(b0 + 8) * TT + t]; }
        #pragma unroll
        for (int pp = 0; pp < 2; ++pp) {
            const int j = bx * 16 + wn * 8 + pp * 4 + q;
            float gi0 = acc[mt][2*pp][0],   gf0 = acc[mt][2*pp][1];
            float gi1 = acc[mt][2*pp][2],   gf1 = acc[mt][2*pp][3];
            float gg0 = acc[mt][2*pp+1][0], go0 = acc[mt][2*pp+1][1];
            float gg1 = acc[mt][2*pp+1][2], go1 = acc[mt][2*pp+1][3];
            if (LAYER == 0) {
                const int m0 = bx * 64 + wn * 32 + pp * 16 + 2 * q;
                float2 u;
                u = *(const float2*)(g_bias1 + v0 * G4H + m0);     gi0 += u.x; gf0 += u.y;
                u = *(const float2*)(g_bias1 + v0 * G4H + m0 + 8); gg0 += u.x; go0 += u.y;
                u = *(const float2*)(g_bias1 + v1 * G4H + m0);     gi1 += u.x; gf1 += u.y;
                u = *(const float2*)(g_bias1 + v1 * G4H + m0 + 8); gg1 += u.x; go1 += u.y;
            }
            {
                const int idx = b0 * HH + j;
                float co = cst[idx];
                float cn = sigf(gf0) * co + sigf(gi0) * tanhp(gg0);
                cst[idx] = cn;
                float hn = sigf(go0) * tanhp(cn);
                __nv_bfloat16 hh = __float2bfloat16(hn);
                Ohi[idx] = hh;
                Olo[idx] = __float2bfloat16(hn - __bfloat162float(hh));
            }
            {
                const int idx = (b0 + 8) * HH + j;
                float co = cst[idx];
                float cn = sigf(gf1) * co + sigf(gi1) * tanhp(gg1);
                cst[idx] = cn;
                float hn = sigf(go1) * tanhp(cn);
                __nv_bfloat16 hh = __float2bfloat16(hn);
                Ohi[idx] = hh;
                Olo[idx] = __float2bfloat16(hn - __bfloat162float(hh));
            }
        }
    }
}

// =========================================================================
// packing / init / fc / finalize
// =========================================================================
__global__ void pack_w1(const float* __restrict__ Whh0) {
    int idx = blockIdx.x * 256 + threadIdx.x;
    if (idx < G4H * 256) {
        int m = idx >> 8, k = idx & 255;
        float w = Whh0[orig_row(m) * HH + k];
        __nv_bfloat16 hi = __float2bfloat16(w);
        g_W1hi[idx] = hi;
        g_W1lo[idx] = __float2bfloat16(w - __bfloat162float(hi));
    }
}
__global__ void pack_w2(const float* __restrict__ Wih1, const float* __restrict__ Whh1) {
    int idx = blockIdx.x * 256 + threadIdx.x;
    if (idx < G4H * 512) {
        int m = idx >> 9, k = idx & 511;
        int row = orig_row(m);
        float w = (k < HH) ? Wih1[row * HH + k] : Whh1[row * HH + k - HH];
        __nv_bfloat16 hi = __float2bfloat16(w);
        g_W2hi[idx] = hi;
        g_W2lo[idx] = __float2bfloat16(w - __bfloat162float(hi));
    }
}
__global__ void pack_bias1(const float* __restrict__ emb, const float* __restrict__ Wih0) {
    int idx = blockIdx.x * 256 + threadIdx.x;
    if (idx < VV * G4H) {
        int v = idx >> 10, m = idx & 1023;
        int row = orig_row(m);
        float s = 0.f;
        #pragma unroll
        for (int d = 0; d < DIN; ++d) s += emb[v * DIN + d] * Wih0[row * DIN + d];
        g_bias1[idx] = s;
    }
}
__global__ void init_state(const float* __restrict__ h0, const float* __restrict__ c0) {
    int i = blockIdx.x * 256 + threadIdx.x;
    if (i < BH) {
        float a = h0[i], b = h0[BH + i];
        __nv_bfloat16 ah = __float2bfloat16(a), bh = __float2bfloat16(b);
        g_h1hi[0][i] = ah; g_h1lo[0][i] = __float2bfloat16(a - __bfloat162float(ah));
        g_h2hi[0][i] = bh; g_h2lo[0][i] = __float2bfloat16(b - __bfloat162float(bh));
        g_c1[i] = c0[i];
        g_c2[i] = c0[BH + i];
    }
}
__global__ void fc_kernel(const float* __restrict__ Wf, const float* __restrict__ bf,
                          float* __restrict__ out)
{
    __shared__ float hs[8][HH];
    const int b0 = blockIdx.x * 8;
    for (int i = threadIdx.x; i < 8 * HH; i += 256) {
        int idx = (b0 + i / HH) * HH + (i % HH);
        hs[i / HH][i % HH] = __bfloat162float(g_h2hi[0][idx]) + __bfloat162float(g_h2lo[0][idx]);
    }
    __syncthreads();
    for (int idx = threadIdx.x; idx < 8 * VV; idx += 256) {
        const int bl = idx / VV, v = idx % VV;
        const float* __restrict__ wr = Wf + v * HH;
        const float* __restrict__ hp = hs[bl];
        float s = bf[v];
        #pragma unroll 8
        for (int k = 0; k < HH; k++) s += hp[k] * wr[k];
        out[(b0 + bl) * VV + v] = s;
    }
}
__global__ void finalize(float* __restrict__ out) {
    int i = blockIdx.x * 256 + threadIdx.x;
    if (i < BH) {
        out[OFF_H + i]      = __bfloat162float(g_h1hi[0][i]) + __bfloat162float(g_h1lo[0][i]);
        out[OFF_H + BH + i] = __bfloat162float(g_h2hi[0][i]) + __bfloat162float(g_h2lo[0][i]);
        out[OFF_C + i]      = g_c1[i];
        out[OFF_C + BH + i] = g_c2[i];
    }
}

// =========================================================================
extern "C" void kernel_launch(void* const* d_in, const int* in_sizes, int n_in,
                              void* d_out, int out_size)
{
    const int*   x    = (const int*)  d_in[0];
    const float* h0   = (const float*)d_in[1];
    const float* c0   = (const float*)d_in[2];
    const float* emb  = (const float*)d_in[3];
    const float* Wih0 = (const float*)d_in[4];
    const float* Whh0 = (const float*)d_in[5];
    const float* Wih1 = (const float*)d_in[6];
    const float* Whh1 = (const float*)d_in[7];
    const float* fcW  = (const float*)d_in[8];
    const float* fcb  = (const float*)d_in[9];
    float* out = (float*)d_out;

    cudaFuncSetAttribute(lstm_mma<4,0>, cudaFuncAttributeMaxDynamicSharedMemorySize, SMEM_TOTAL);
    cudaFuncSetAttribute(lstm_mma<8,1>, cudaFuncAttributeMaxDynamicSharedMemorySize, SMEM_TOTAL);

    pack_w1   <<<(G4H*256 + 255) / 256, 256>>>(Whh0);
    pack_w2   <<<(G4H*512 + 255) / 256, 256>>>(Wih1, Whh1);
    pack_bias1<<<(VV*G4H  + 255) / 256, 256>>>(emb, Wih0);
    init_state<<<(BH      + 255) / 256, 256>>>(h0, c0);

    dim3 grid(16, 32);   // 16 n-tiles (1024/64) x 32 m-tiles (4096/128)
    for (int t = 0; t < TT; t++) {
        const int p = t & 1;
        lstm_mma<4,0><<<grid, 256, SMEM_TOTAL>>>(x, t, p);
        lstm_mma<8,1><<<grid, 256, SMEM_TOTAL>>>(x, t, p);
    }

    fc_kernel<<<BB / 8, 256>>>(fcW, fcb, out);
    finalize <<<(BH + 255) / 256, 256>>>(out);
}

// round 5
// speedup vs baseline: 3.6222x; 1.4317x over previous
#include <cuda_runtime.h>
#include <cuda_fp16.h>
#include <cuda_bf16.h>
#include <cstdint>

#define BB    4096
#define TT    80
#define HH    256
#define DIN   8
#define VV    80
#define G4H   1024
#define BH    (BB*HH)
#define OFF_H (BB*VV)
#define OFF_C (OFF_H + 2*BH)

// ---------------- device scratch (no allocation allowed) ----------------
__device__ __half g_W1hi[G4H*256], g_W1lo[G4H*256];   // layer1 hh, packed cols, K contig
__device__ __half g_W2hi[G4H*512], g_W2lo[G4H*512];   // layer2 [ih | hh]
__device__ float  g_bias1[VV*G4H];                     // (W_ih0 @ emb[v]) packed col order
__device__ __half g_h1[2][BH], g_h2[2][BH];            // fp16 recurrent state (ping-pong)
__device__ float  g_h1f[BH], g_h2f[BH];                // fp32 shadow of latest h (for outputs)
__device__ float  g_c1[BH], g_c2[BH];

// packed column m -> original gate row (g*H + j); one thread's HMMA accum cols
// over an n8-tile-pair = gates i,f,g,o of one hidden unit j
__host__ __device__ __forceinline__ int orig_row(int m) {
    int j = 4 * (m >> 4) + ((m >> 1) & 3);
    int g = (m & 1) | (((m >> 3) & 1) << 1);
    return g * HH + j;
}

// ---------------- PTX helpers ----------------
__device__ __forceinline__ uint32_t smem_u32(const void* p) {
    uint32_t a;
    asm("{ .reg .u64 t; cvta.to.shared.u64 t, %1; cvt.u32.u64 %0, t; }" : "=r"(a) : "l"(p));
    return a;
}
__device__ __forceinline__ void cpa16(uint32_t s, const void* g) {
    asm volatile("cp.async.cg.shared.global [%0], [%1], 16;" :: "r"(s), "l"(g));
}
__device__ __forceinline__ void cpa_commit() {
    asm volatile("cp.async.commit_group;" ::: "memory");
}
template<int N>
__device__ __forceinline__ void cpa_wait() {
    asm volatile("cp.async.wait_group %0;" :: "n"(N) : "memory");
}
__device__ __forceinline__ void ldsm4(uint32_t* r, uint32_t addr) {
    asm volatile("ldmatrix.sync.aligned.m8n8.x4.shared.b16 {%0,%1,%2,%3}, [%4];"
                 : "=r"(r[0]), "=r"(r[1]), "=r"(r[2]), "=r"(r[3]) : "r"(addr));
}
__device__ __forceinline__ void mma16816h(float* c, const uint32_t* a, uint32_t b0, uint32_t b1) {
    asm volatile(
        "mma.sync.aligned.m16n8k16.row.col.f32.f16.f16.f32 "
        "{%0,%1,%2,%3}, {%4,%5,%6,%7}, {%8,%9}, {%0,%1,%2,%3};"
        : "+f"(c[0]), "+f"(c[1]), "+f"(c[2]), "+f"(c[3])
        : "r"(a[0]), "r"(a[1]), "r"(a[2]), "r"(a[3]), "r"(b0), "r"(b1));
}

__device__ __forceinline__ float sigf(float x)  { return 1.0f / (1.0f + __expf(-x)); }
__device__ __forceinline__ float tanhp(float x) { return 2.0f * sigf(2.0f * x) - 1.0f; }

// SMEM stage: A 16K | Bhi 16K | Blo 16K  (128B rows, SW128 swizzle), 2 stages
#define STG 49152
#define SMEM_TOTAL (2*STG)

// =========================================================================
// Fused HMMA LSTM step, both layers in one launch.
//   which==1 (layer1 @ t1): K=256 (nc=4), A = h1[p1]
//   which==0 (layer2 @ t2): K=512 (nc=8), A = [h1_cur | h2_prev]
// CTA tile: M=128 x N=128 packed cols. 8 warps (4M x 2N) of 32x64.
// mode: 0 = z0->layer2(t2), z1->layer1(t1); 1 = layer1 only; 2 = layer2 only
// =========================================================================
__global__ void __launch_bounds__(256, 2) lstm_step(const int* __restrict__ x,
                                                    int t2, int t1, int mode)
{
    extern __shared__ char sm[];
    const uint32_t smb = smem_u32(sm);
    const int tid  = threadIdx.x;
    const int lane = tid & 31, wid = tid >> 5;
    const int wm = wid & 3, wn = wid >> 2;
    const int bx = blockIdx.x;             // 0..7 n-tiles (128 packed cols each)
    const int by = blockIdx.y;             // 0..31 m-tiles
    const int mbase = by * 128, nb = bx * 128;

    const int which = (mode == 0) ? (int)blockIdx.z : (mode == 2 ? 0 : 1);

    int nc, KW, tt;
    const __half *Whi, *Wlo, *A0, *A1;
    __half* Oh;
    float *Of, *cst;
    if (which == 1) {                       // layer 1 at time t1
        const int p = t1 & 1;
        nc = 4; KW = 256; tt = t1;
        Whi = g_W1hi; Wlo = g_W1lo;
        A0 = g_h1[p]; A1 = A0;
        Oh = g_h1[p ^ 1]; Of = g_h1f; cst = g_c1;
    } else {                                // layer 2 at time t2
        const int p = t2 & 1;
        nc = 8; KW = 512; tt = t2;
        Whi = g_W2hi; Wlo = g_W2lo;
        A0 = g_h1[p ^ 1];                   // h1 at current t2
        A1 = g_h2[p];                       // h2 at t2-1
        Oh = g_h2[p ^ 1]; Of = g_h2f; cst = g_c2;
    }

    float acc[2][8][4];
    #pragma unroll
    for (int i = 0; i < 2; i++)
        #pragma unroll
        for (int j = 0; j < 8; j++)
            #pragma unroll
            for (int k = 0; k < 4; k++) acc[i][j][k] = 0.f;

    auto load_chunk = [&](int c) {
        const uint32_t sb = smb + (c & 1) * STG;
        const __half* ap = (c < 4) ? A0 : A1;
        const int ko = (c & 3) * 64;
        #pragma unroll
        for (int it = 0; it < 4; ++it) {                 // A: 128 rows x 8 16B-chunks
            const int idx = tid + it * 256;
            const int row = idx >> 3, ch = idx & 7;
            const uint32_t so = (uint32_t)((row * 128 + ch * 16) ^ ((row & 7) << 4));
            cpa16(sb + so, ap + (mbase + row) * HH + ko + ch * 8);
        }
        #pragma unroll
        for (int it = 0; it < 4; ++it) {                 // B: 128 rows x 8 chunks x 2 planes
            const int idx = tid + it * 256;
            const int row = idx >> 3, ch = idx & 7;
            const uint32_t so = (uint32_t)((row * 128 + ch * 16) ^ ((row & 7) << 4));
            const int gw = (nb + row) * KW + c * 64 + ch * 8;
            cpa16(sb + 16384 + so, Whi + gw);
            cpa16(sb + 32768 + so, Wlo + gw);
        }
        cpa_commit();
    };

    load_chunk(0);
    for (int c = 0; c < nc; ++c) {
        if (c + 1 < nc) { load_chunk(c + 1); cpa_wait<1>(); }
        else            { cpa_wait<0>(); }
        __syncthreads();

        const uint32_t sb = smb + (c & 1) * STG;
        #pragma unroll
        for (int ks = 0; ks < 4; ++ks) {
            uint32_t af[2][4];
            #pragma unroll
            for (int mt = 0; mt < 2; ++mt) {
                const int row  = wm * 32 + mt * 16 + (lane & 15);
                const uint32_t so = (uint32_t)((row * 128 + ks * 32 + ((lane >> 4) & 1) * 16)
                                               ^ ((row & 7) << 4));
                ldsm4(af[mt], sb + so);
            }
            #pragma unroll
            for (int np = 0; np < 4; ++np) {
                uint32_t bh[4], bl[4];
                const int brow = wn * 64 + np * 16 + (lane & 7) + ((lane >> 4) & 1) * 8;
                const uint32_t so = (uint32_t)((brow * 128 + ks * 32 + ((lane >> 3) & 1) * 16)
                                               ^ ((brow & 7) << 4));
                ldsm4(bh, sb + 16384 + so);
                ldsm4(bl, sb + 32768 + so);
                #pragma unroll
                for (int mt = 0; mt < 2; ++mt)
                    #pragma unroll
                    for (int h = 0; h < 2; ++h) {
                        mma16816h(acc[mt][2*np + h], af[mt], bh[2*h], bh[2*h + 1]);
                        mma16816h(acc[mt][2*np + h], af[mt], bl[2*h], bl[2*h + 1]);
                    }
            }
        }
        __syncthreads();
    }

    // ---- fused LSTM epilogue: all 4 gates of (b, j) live in this thread ----
    const int r = lane >> 2, q = lane & 3;
    #pragma unroll
    for (int mt = 0; mt < 2; ++mt) {
        const int b0 = mbase + wm * 32 + mt * 16 + r;
        int v0 = 0, v1 = 0;
        if (which == 1) { v0 = x[b0 * TT + tt]; v1 = x[(b0 + 8) * TT + tt]; }
        #pragma unroll
        for (int np = 0; np < 4; ++np) {
            const int j = bx * 32 + wn * 16 + np * 4 + q;
            float gi0 = acc[mt][2*np][0],   gf0 = acc[mt][2*np][1];
            float gi1 = acc[mt][2*np][2],   gf1 = acc[mt][2*np][3];
            float gg0 = acc[mt][2*np+1][0], go0 = acc[mt][2*np+1][1];
            float gg1 = acc[mt][2*np+1][2], go1 = acc[mt][2*np+1][3];
            if (which == 1) {
                const int m0 = bx * 128 + wn * 64 + np * 16 + 2 * q;
                float2 u;
                u = *(const float2*)(g_bias1 + v0 * G4H + m0);     gi0 += u.x; gf0 += u.y;
                u = *(const float2*)(g_bias1 + v0 * G4H + m0 + 8); gg0 += u.x; go0 += u.y;
                u = *(const float2*)(g_bias1 + v1 * G4H + m0);     gi1 += u.x; gf1 += u.y;
                u = *(const float2*)(g_bias1 + v1 * G4H + m0 + 8); gg1 += u.x; go1 += u.y;
            }
            {
                const int idx = b0 * HH + j;
                float co = cst[idx];
                float cn = sigf(gf0) * co + sigf(gi0) * tanhp(gg0);
                cst[idx] = cn;
                float hn = sigf(go0) * tanhp(cn);
                Oh[idx] = __float2half(hn);
                Of[idx] = hn;
            }
            {
                const int idx = (b0 + 8) * HH + j;
                float co = cst[idx];
                float cn = sigf(gf1) * co + sigf(gi1) * tanhp(gg1);
                cst[idx] = cn;
                float hn = sigf(go1) * tanhp(cn);
                Oh[idx] = __float2half(hn);
                Of[idx] = hn;
            }
        }
    }
}

// =========================================================================
// packing / init / fc / finalize
// =========================================================================
__global__ void pack_w1(const float* __restrict__ Whh0) {
    int idx = blockIdx.x * 256 + threadIdx.x;
    if (idx < G4H * 256) {
        int m = idx >> 8, k = idx & 255;
        float w = Whh0[orig_row(m) * HH + k];
        __half hi = __float2half(w);
        g_W1hi[idx] = hi;
        g_W1lo[idx] = __float2half(w - __half2float(hi));
    }
}
__global__ void pack_w2(const float* __restrict__ Wih1, const float* __restrict__ Whh1) {
    int idx = blockIdx.x * 256 + threadIdx.x;
    if (idx < G4H * 512) {
        int m = idx >> 9, k = idx & 511;
        int row = orig_row(m);
        float w = (k < HH) ? Wih1[row * HH + k] : Whh1[row * HH + k - HH];
        __half hi = __float2half(w);
        g_W2hi[idx] = hi;
        g_W2lo[idx] = __float2half(w - __half2float(hi));
    }
}
__global__ void pack_bias1(const float* __restrict__ emb, const float* __restrict__ Wih0) {
    int idx = blockIdx.x * 256 + threadIdx.x;
    if (idx < VV * G4H) {
        int v = idx >> 10, m = idx & 1023;
        int row = orig_row(m);
        float s = 0.f;
        #pragma unroll
        for (int d = 0; d < DIN; ++d) s += emb[v * DIN + d] * Wih0[row * DIN + d];
        g_bias1[idx] = s;
    }
}
__global__ void init_state(const float* __restrict__ h0, const float* __restrict__ c0) {
    int i = blockIdx.x * 256 + threadIdx.x;
    if (i < BH) {
        float a = h0[i], b = h0[BH + i];
        g_h1[0][i] = __float2half(a);  g_h1f[i] = a;
        g_h2[0][i] = __float2half(b);  g_h2f[i] = b;
        g_c1[i] = c0[i];
        g_c2[i] = c0[BH + i];
    }
}
__global__ void fc_kernel(const float* __restrict__ Wf, const float* __restrict__ bf,
                          float* __restrict__ out)
{
    __shared__ float hs[8][HH];
    const int b0 = blockIdx.x * 8;
    for (int i = threadIdx.x; i < 8 * HH; i += 256)
        hs[i / HH][i % HH] = g_h2f[(b0 + i / HH) * HH + (i % HH)];
    __syncthreads();
    for (int idx = threadIdx.x; idx < 8 * VV; idx += 256) {
        const int bl = idx / VV, v = idx % VV;
        const float* __restrict__ wr = Wf + v * HH;
        const float* __restrict__ hp = hs[bl];
        float s = bf[v];
        #pragma unroll 8
        for (int k = 0; k < HH; k++) s += hp[k] * wr[k];
        out[(b0 + bl) * VV + v] = s;
    }
}
__global__ void finalize(float* __restrict__ out) {
    int i = blockIdx.x * 256 + threadIdx.x;
    if (i < BH) {
        out[OFF_H + i]      = g_h1f[i];
        out[OFF_H + BH + i] = g_h2f[i];
        out[OFF_C + i]      = g_c1[i];
        out[OFF_C + BH + i] = g_c2[i];
    }
}

// =========================================================================
extern "C" void kernel_launch(void* const* d_in, const int* in_sizes, int n_in,
                              void* d_out, int out_size)
{
    const int*   x    = (const int*)  d_in[0];
    const float* h0   = (const float*)d_in[1];
    const float* c0   = (const float*)d_in[2];
    const float* emb  = (const float*)d_in[3];
    const float* Wih0 = (const float*)d_in[4];
    const float* Whh0 = (const float*)d_in[5];
    const float* Wih1 = (const float*)d_in[6];
    const float* Whh1 = (const float*)d_in[7];
    const float* fcW  = (const float*)d_in[8];
    const float* fcb  = (const float*)d_in[9];
    float* out = (float*)d_out;

    cudaFuncSetAttribute(lstm_step, cudaFuncAttributeMaxDynamicSharedMemorySize, SMEM_TOTAL);

    pack_w1   <<<(G4H*256 + 255) / 256, 256>>>(Whh0);
    pack_w2   <<<(G4H*512 + 255) / 256, 256>>>(Wih1, Whh1);
    pack_bias1<<<(VV*G4H  + 255) / 256, 256>>>(emb, Wih0);
    init_state<<<(BH      + 255) / 256, 256>>>(h0, c0);

    // layer1(0); then fused {layer2(t), layer1(t+1)} for t=0..78; then layer2(79)
    lstm_step<<<dim3(8, 32, 1), 256, SMEM_TOTAL>>>(x, 0, 0, 1);
    for (int t = 0; t < TT - 1; ++t)
        lstm_step<<<dim3(8, 32, 2), 256, SMEM_TOTAL>>>(x, t, t + 1, 0);
    lstm_step<<<dim3(8, 32, 1), 256, SMEM_TOTAL>>>(x, TT - 1, 0, 2);

    fc_kernel<<<BB / 8, 256>>>(fcW, fcb, out);
    finalize <<<(BH + 255) / 256, 256>>>(out);
}